// round 11
// baseline (speedup 1.0000x reference)
#include <cuda_runtime.h>
#include <cstdint>

#define N_NODES 50000
#define D_IN    128
#define D_H     128
#define D_Z2    64
#define D_Z     32
#define MAX_E   800000

// -------- device scratch --------
__device__ __align__(16) float d_dinv[N_NODES];
__device__ __align__(16) int   d_cnt [N_NODES];
__device__ __align__(16) int   d_cur [N_NODES + 4];
__device__ __align__(16) int   d_rs  [N_NODES + 4];
__device__ __align__(16) int   d_part[64];
__device__ __align__(16) int   d_csr [MAX_E];
__device__ __align__(16) float d_g1  [N_NODES * D_H];   // h0 = x@W1 (unscaled)
__device__ __align__(16) float d_g2  [N_NODES * D_Z2];  // (A_hat-ish intermediate) * dinv
__device__ __align__(16) float d_Wcat[D_H * D_Z2];

// -------- helpers --------
__device__ __forceinline__ uint32_t tf32_hi(float x) {
    uint32_t u;
    asm("cvt.rna.tf32.f32 %0, %1;" : "=r"(u) : "f"(x));
    return u;
}
__device__ __forceinline__ void tf32_split(float x, uint32_t& hi, uint32_t& lo) {
    hi = tf32_hi(x);
    lo = tf32_hi(x - __uint_as_float(hi));
}
__device__ __forceinline__ void mma_tf32(float c[4], const uint32_t a[4], const uint32_t b[2]) {
    asm volatile(
        "mma.sync.aligned.m16n8k8.row.col.f32.tf32.tf32.f32 "
        "{%0,%1,%2,%3}, {%4,%5,%6,%7}, {%8,%9}, {%0,%1,%2,%3};"
        : "+f"(c[0]), "+f"(c[1]), "+f"(c[2]), "+f"(c[3])
        : "r"(a[0]), "r"(a[1]), "r"(a[2]), "r"(a[3]), "r"(b[0]), "r"(b[1]));
}

// -------- CSR build --------
__global__ void zero_wcat_kernel(int* __restrict__ cnt, float* __restrict__ Wcat,
                                 const float* __restrict__ Wmu, const float* __restrict__ Wls,
                                 int n) {
    int i = blockIdx.x * blockDim.x + threadIdx.x;
    if (i < n) cnt[i] = 0;
    int j = i - n;
    if (j >= 0 && j < D_H * D_Z2) {
        int k = j / D_Z2, c = j % D_Z2;
        Wcat[j] = (c < D_Z) ? Wmu[k * D_Z + c] : Wls[k * D_Z + (c - D_Z)];
    }
}

__global__ void hist2_kernel(int* __restrict__ cnt,
                             const int* __restrict__ dst1, int E1,
                             const int* __restrict__ dst2, int E2) {
    int i = blockIdx.x * blockDim.x + threadIdx.x;
    if (i < E1 + E2) {
        int d = (i < E1) ? dst1[i] : dst2[i - E1];
        atomicAdd(&cnt[d], 1);
    }
}

__global__ void partial_kernel(const int* __restrict__ cnt, int* __restrict__ part, int n) {
    __shared__ int sh[256];
    int t = threadIdx.x;
    int i = blockIdx.x * 1024 + t * 4;
    int s = 0;
    if (i < n) {
        int4 v = *reinterpret_cast<const int4*>(cnt + i);
        s = v.x + v.y + v.z + v.w;
    }
    sh[t] = s;
    __syncthreads();
    for (int off = 128; off > 0; off >>= 1) {
        if (t < off) sh[t] += sh[t + off];
        __syncthreads();
    }
    if (t == 0) part[blockIdx.x] = sh[0];
}

__global__ void scan_write_kernel(const int* __restrict__ cnt, const int* __restrict__ part,
                                  int* __restrict__ rs, int* __restrict__ cur,
                                  float* __restrict__ dinv, int n, int nblk) {
    __shared__ int sh[256];
    __shared__ int base_s;
    int t = threadIdx.x;
    int b = blockIdx.x;
    if (t == 0) {
        int base = 0;
        for (int j = 0; j < b; j++) base += part[j];
        base_s = base;
        if (b == 0) {
            int tot = 0;
            for (int j = 0; j < nblk; j++) tot += part[j];
            rs[n] = tot;
        }
    }
    int i = b * 1024 + t * 4;
    int4 v = make_int4(0, 0, 0, 0);
    if (i < n) v = *reinterpret_cast<const int4*>(cnt + i);
    int s = v.x + v.y + v.z + v.w;
    sh[t] = s;
    __syncthreads();
    for (int off = 1; off < 256; off <<= 1) {
        int tmp = (t >= off) ? sh[t - off] : 0;
        __syncthreads();
        sh[t] += tmp;
        __syncthreads();
    }
    int thrbase = base_s + sh[t] - s;
    if (i < n) {
        int r0 = thrbase;
        rs[i]     = r0; cur[i]     = r0; dinv[i]     = rsqrtf((float)(v.x + 1));
        int r1 = r0 + v.x;
        rs[i + 1] = r1; cur[i + 1] = r1; dinv[i + 1] = rsqrtf((float)(v.y + 1));
        int r2 = r1 + v.y;
        rs[i + 2] = r2; cur[i + 2] = r2; dinv[i + 2] = rsqrtf((float)(v.z + 1));
        int r3 = r2 + v.z;
        rs[i + 3] = r3; cur[i + 3] = r3; dinv[i + 3] = rsqrtf((float)(v.w + 1));
    }
}

__global__ void scatter2_kernel(const int* __restrict__ src1, const int* __restrict__ dst1, int E1,
                                const int* __restrict__ src2, const int* __restrict__ dst2, int E2,
                                int* __restrict__ cur, int* __restrict__ csr) {
    int i = blockIdx.x * blockDim.x + threadIdx.x;
    if (i < E1 + E2) {
        int s, d;
        if (i < E1) { s = src1[i]; d = dst1[i]; }
        else        { s = src2[i - E1]; d = dst2[i - E1]; }
        int pos = atomicAdd(&cur[d], 1);
        csr[pos] = s;
    }
}

// ==================== GEMM1: 3xTF32, h0 = x@W1 (unscaled) ====================
__global__ __launch_bounds__(256) void mma_gemm1_kernel(
    const float* __restrict__ X, const float* __restrict__ W,
    float* __restrict__ g, int nrows)
{
    constexpr int NOUT = 128;
    constexpr int WN = 64, NT = 8, LDA = 36;
    __shared__ float As[128 * LDA];
    __shared__ float Bs[NOUT * LDA];

    const int tid = threadIdx.x;
    const int wid = tid >> 5, lane = tid & 31;
    const int wm = wid & 3, wn = wid >> 2;
    const int row0 = blockIdx.x * 128;
    const int qid = lane >> 2, qt = lane & 3;

    float acc[2][NT][4];
#pragma unroll
    for (int mi = 0; mi < 2; mi++)
#pragma unroll
        for (int ni = 0; ni < NT; ni++)
#pragma unroll
            for (int j = 0; j < 4; j++) acc[mi][ni][j] = 0.0f;

    for (int c = 0; c < 4; c++) {
#pragma unroll
        for (int i = tid; i < 1024; i += 256) {
            int r = i >> 3, c4 = (i & 7) * 4;
            float4 v = make_float4(0.f, 0.f, 0.f, 0.f);
            if (row0 + r < nrows)
                v = *reinterpret_cast<const float4*>(X + (size_t)(row0 + r) * 128 + c * 32 + c4);
            *reinterpret_cast<float4*>(&As[r * LDA + c4]) = v;
        }
#pragma unroll
        for (int i = tid; i < NOUT * 32; i += 256) {
            int nn = i % NOUT, kk = i / NOUT;
            Bs[nn * LDA + kk] = W[(size_t)(c * 32 + kk) * NOUT + nn];
        }
        __syncthreads();

#pragma unroll
        for (int ks = 0; ks < 4; ks++) {
            uint32_t ahi[2][4], alo[2][4];
#pragma unroll
            for (int mi = 0; mi < 2; mi++) {
                int r = wm * 32 + mi * 16 + qid;
                int k = ks * 8 + qt;
                tf32_split(As[r * LDA + k],           ahi[mi][0], alo[mi][0]);
                tf32_split(As[(r + 8) * LDA + k],     ahi[mi][1], alo[mi][1]);
                tf32_split(As[r * LDA + k + 4],       ahi[mi][2], alo[mi][2]);
                tf32_split(As[(r + 8) * LDA + k + 4], ahi[mi][3], alo[mi][3]);
            }
#pragma unroll
            for (int ni = 0; ni < NT; ni++) {
                int nn = wn * WN + ni * 8 + qid;
                int k = ks * 8 + qt;
                uint32_t bhi[2], blo[2];
                tf32_split(Bs[nn * LDA + k],     bhi[0], blo[0]);
                tf32_split(Bs[nn * LDA + k + 4], bhi[1], blo[1]);
#pragma unroll
                for (int mi = 0; mi < 2; mi++) {
                    mma_tf32(acc[mi][ni], ahi[mi], blo);
                    mma_tf32(acc[mi][ni], alo[mi], bhi);
                    mma_tf32(acc[mi][ni], ahi[mi], bhi);
                }
            }
        }
        __syncthreads();
    }

#pragma unroll
    for (int mi = 0; mi < 2; mi++) {
        int r0 = row0 + wm * 32 + mi * 16 + qid;
        int r1 = r0 + 8;
#pragma unroll
        for (int ni = 0; ni < NT; ni++) {
            int col = wn * WN + ni * 8 + qt * 2;
            if (r0 < nrows) {
                float2 o = make_float2(acc[mi][ni][0], acc[mi][ni][1]);
                *reinterpret_cast<float2*>(g + (size_t)r0 * NOUT + col) = o;
            }
            if (r1 < nrows) {
                float2 o = make_float2(acc[mi][ni][2], acc[mi][ni][3]);
                *reinterpret_cast<float2*>(g + (size_t)r1 * NOUT + col) = o;
            }
        }
    }
}

// ==================== FUSED layer-1 agg + layer-2 GEMM ====================
// Block = 128-node tile. Phase 1: each warp gathers/aggregates 16 h-rows into
// the A smem tile (relu+bias fused). Phase 2: g2 = (h_tile @ Wcat) * dinv.
// A tile layout As[r*132 + k] (bank = (4r+k)%32, conflict-free fragments).
__global__ __launch_bounds__(256) void layer12_kernel(
    const int* __restrict__ rs, const int* __restrict__ csr,
    const float* __restrict__ h0, const float* __restrict__ dinv,
    const float* __restrict__ b1, const float* __restrict__ Wcat,
    float* __restrict__ g2, int n)
{
    constexpr int LDA = 132;
    extern __shared__ float sm[];
    float* As = sm;                    // 128 * 132
    float* Bs = sm + 128 * LDA;        // 64  * 132

    const int tid = threadIdx.x;
    const int wid = tid >> 5, lane = tid & 31;
    const int row0 = blockIdx.x * 128;

    // ---- load Bs: Bs[nn*LDA + kk] = Wcat[kk*64 + nn] ----
    for (int i = tid; i < 64 * 128; i += 256) {
        int nn = i & 63, kk = i >> 6;
        Bs[nn * LDA + kk] = Wcat[kk * 64 + nn];
    }

    // ---- phase 1: aggregate 16 nodes per warp into As ----
    {
        const float4* gv = reinterpret_cast<const float4*>(h0);
        float4 bb = reinterpret_cast<const float4*>(b1)[lane];
        for (int i = 0; i < 16; i++) {
            int local = (wid << 4) + i;
            int d = row0 + local;
            float* arow = As + local * LDA;
            if (d < n) {
                float wd = dinv[d];
                float4 sv = gv[(size_t)d * 32 + lane];
                float4 a0 = make_float4(sv.x * wd, sv.y * wd, sv.z * wd, sv.w * wd);
                float4 a1 = make_float4(0.f, 0.f, 0.f, 0.f);
                float4 a2 = make_float4(0.f, 0.f, 0.f, 0.f);
                float4 a3 = make_float4(0.f, 0.f, 0.f, 0.f);
                int e = rs[d], end = rs[d + 1];
                for (; e + 4 <= end; e += 4) {
                    int s0 = __ldg(&csr[e]);
                    int s1 = __ldg(&csr[e + 1]);
                    int s2 = __ldg(&csr[e + 2]);
                    int s3 = __ldg(&csr[e + 3]);
                    float w0 = __ldg(&dinv[s0]);
                    float w1 = __ldg(&dinv[s1]);
                    float w2 = __ldg(&dinv[s2]);
                    float w3 = __ldg(&dinv[s3]);
                    float4 v0 = gv[(size_t)s0 * 32 + lane];
                    float4 v1 = gv[(size_t)s1 * 32 + lane];
                    float4 v2 = gv[(size_t)s2 * 32 + lane];
                    float4 v3 = gv[(size_t)s3 * 32 + lane];
                    a0.x = fmaf(v0.x, w0, a0.x); a0.y = fmaf(v0.y, w0, a0.y);
                    a0.z = fmaf(v0.z, w0, a0.z); a0.w = fmaf(v0.w, w0, a0.w);
                    a1.x = fmaf(v1.x, w1, a1.x); a1.y = fmaf(v1.y, w1, a1.y);
                    a1.z = fmaf(v1.z, w1, a1.z); a1.w = fmaf(v1.w, w1, a1.w);
                    a2.x = fmaf(v2.x, w2, a2.x); a2.y = fmaf(v2.y, w2, a2.y);
                    a2.z = fmaf(v2.z, w2, a2.z); a2.w = fmaf(v2.w, w2, a2.w);
                    a3.x = fmaf(v3.x, w3, a3.x); a3.y = fmaf(v3.y, w3, a3.y);
                    a3.z = fmaf(v3.z, w3, a3.z); a3.w = fmaf(v3.w, w3, a3.w);
                }
                for (; e < end; e++) {
                    int s0 = __ldg(&csr[e]);
                    float w0 = __ldg(&dinv[s0]);
                    float4 v0 = gv[(size_t)s0 * 32 + lane];
                    a0.x = fmaf(v0.x, w0, a0.x); a0.y = fmaf(v0.y, w0, a0.y);
                    a0.z = fmaf(v0.z, w0, a0.z); a0.w = fmaf(v0.w, w0, a0.w);
                }
                float sx = (a0.x + a1.x) + (a2.x + a3.x);
                float sy = (a0.y + a1.y) + (a2.y + a3.y);
                float sz = (a0.z + a1.z) + (a2.z + a3.z);
                float sw = (a0.w + a1.w) + (a2.w + a3.w);
                float4 r;
                r.x = fmaxf(fmaf(sx, wd, bb.x), 0.f);
                r.y = fmaxf(fmaf(sy, wd, bb.y), 0.f);
                r.z = fmaxf(fmaf(sz, wd, bb.z), 0.f);
                r.w = fmaxf(fmaf(sw, wd, bb.w), 0.f);
                *reinterpret_cast<float4*>(arow + lane * 4) = r;
            } else {
                *reinterpret_cast<float4*>(arow + lane * 4) = make_float4(0.f, 0.f, 0.f, 0.f);
            }
        }
    }
    __syncthreads();

    // ---- phase 2: 3xTF32 GEMM, NOUT=64, K=128 ----
    const int wm = wid & 3, wn = wid >> 2;
    const int qid = lane >> 2, qt = lane & 3;
    constexpr int WN = 32, NT = 4;

    float acc[2][NT][4];
#pragma unroll
    for (int mi = 0; mi < 2; mi++)
#pragma unroll
        for (int ni = 0; ni < NT; ni++)
#pragma unroll
            for (int j = 0; j < 4; j++) acc[mi][ni][j] = 0.0f;

#pragma unroll 4
    for (int ks = 0; ks < 16; ks++) {
        uint32_t ahi[2][4], alo[2][4];
#pragma unroll
        for (int mi = 0; mi < 2; mi++) {
            int r = wm * 32 + mi * 16 + qid;
            int k = ks * 8 + qt;
            tf32_split(As[r * LDA + k],           ahi[mi][0], alo[mi][0]);
            tf32_split(As[(r + 8) * LDA + k],     ahi[mi][1], alo[mi][1]);
            tf32_split(As[r * LDA + k + 4],       ahi[mi][2], alo[mi][2]);
            tf32_split(As[(r + 8) * LDA + k + 4], ahi[mi][3], alo[mi][3]);
        }
#pragma unroll
        for (int ni = 0; ni < NT; ni++) {
            int nn = wn * WN + ni * 8 + qid;
            int k = ks * 8 + qt;
            uint32_t bhi[2], blo[2];
            tf32_split(Bs[nn * LDA + k],     bhi[0], blo[0]);
            tf32_split(Bs[nn * LDA + k + 4], bhi[1], blo[1]);
#pragma unroll
            for (int mi = 0; mi < 2; mi++) {
                mma_tf32(acc[mi][ni], ahi[mi], blo);
                mma_tf32(acc[mi][ni], alo[mi], bhi);
                mma_tf32(acc[mi][ni], ahi[mi], bhi);
            }
        }
    }

#pragma unroll
    for (int mi = 0; mi < 2; mi++) {
        int r0 = row0 + wm * 32 + mi * 16 + qid;
        int r1 = r0 + 8;
        float w0 = (r0 < n) ? dinv[r0] : 0.f;
        float w1 = (r1 < n) ? dinv[r1] : 0.f;
#pragma unroll
        for (int ni = 0; ni < NT; ni++) {
            int col = wn * WN + ni * 8 + qt * 2;
            if (r0 < n) {
                float2 o = make_float2(acc[mi][ni][0] * w0, acc[mi][ni][1] * w0);
                *reinterpret_cast<float2*>(g2 + (size_t)r0 * 64 + col) = o;
            }
            if (r1 < n) {
                float2 o = make_float2(acc[mi][ni][2] * w1, acc[mi][ni][3] * w1);
                *reinterpret_cast<float2*>(g2 + (size_t)r1 * 64 + col) = o;
            }
        }
    }
}

// -------- agg2 (F=64): fused bias + mu/logstd split --------
__global__ __launch_bounds__(256) void agg2_kernel(
    const int* __restrict__ rs, const int* __restrict__ csr,
    const float* __restrict__ g, const float* __restrict__ dinv,
    const float* __restrict__ bmu, const float* __restrict__ bls,
    float* __restrict__ out, int n)
{
    int d = (blockIdx.x * blockDim.x + threadIdx.x) >> 5;
    int lane = threadIdx.x & 31;
    if (d >= n) return;

    const float2* gv = reinterpret_cast<const float2*>(g);
    float2 a0 = gv[(size_t)d * 32 + lane];
    float2 a1 = make_float2(0.f, 0.f);
    float2 a2 = make_float2(0.f, 0.f);
    float2 a3 = make_float2(0.f, 0.f);

    int e = rs[d], end = rs[d + 1];
    for (; e + 4 <= end; e += 4) {
        int s0 = __ldg(&csr[e]);
        int s1 = __ldg(&csr[e + 1]);
        int s2 = __ldg(&csr[e + 2]);
        int s3 = __ldg(&csr[e + 3]);
        float2 v0 = gv[(size_t)s0 * 32 + lane];
        float2 v1 = gv[(size_t)s1 * 32 + lane];
        float2 v2 = gv[(size_t)s2 * 32 + lane];
        float2 v3 = gv[(size_t)s3 * 32 + lane];
        a0.x += v0.x; a0.y += v0.y;
        a1.x += v1.x; a1.y += v1.y;
        a2.x += v2.x; a2.y += v2.y;
        a3.x += v3.x; a3.y += v3.y;
    }
    for (; e < end; e++) {
        int s0 = __ldg(&csr[e]);
        float2 v0 = gv[(size_t)s0 * 32 + lane];
        a0.x += v0.x; a0.y += v0.y;
    }
    float w = dinv[d];
    float vx = ((a0.x + a1.x) + (a2.x + a3.x)) * w;
    float vy = ((a0.y + a1.y) + (a2.y + a3.y)) * w;
    int c0 = lane * 2, c1 = lane * 2 + 1;
    if (c0 < D_Z) {
        float2 o = make_float2(vx + bmu[c0], vy + bmu[c1]);
        reinterpret_cast<float2*>(out)[(size_t)d * 16 + lane] = o;
    } else {
        float2 o = make_float2(vx + bls[c0 - D_Z], vy + bls[c1 - D_Z]);
        reinterpret_cast<float2*>(out + (size_t)n * D_Z)[(size_t)d * 16 + (lane - 16)] = o;
    }
}

extern "C" void kernel_launch(void* const* d_in, const int* in_sizes, int n_in,
                              void* d_out, int out_size)
{
    const float* x    = (const float*)d_in[0];
    const int*   ei1  = (const int*)d_in[1];
    const int*   ei2  = (const int*)d_in[2];
    const float* W1   = (const float*)d_in[3];
    const float* b1   = (const float*)d_in[4];
    const float* Wmu  = (const float*)d_in[5];
    const float* bmu  = (const float*)d_in[6];
    const float* Wls  = (const float*)d_in[7];
    const float* bls  = (const float*)d_in[8];
    float* out = (float*)d_out;

    static cudaStream_t sB = nullptr;
    static cudaEvent_t evFork = nullptr, evJoin = nullptr;
    if (sB == nullptr) {
        cudaStreamCreateWithFlags(&sB, cudaStreamNonBlocking);
        cudaEventCreateWithFlags(&evFork, cudaEventDisableTiming);
        cudaEventCreateWithFlags(&evJoin, cudaEventDisableTiming);
        cudaFuncSetAttribute(layer12_kernel, cudaFuncAttributeMaxDynamicSharedMemorySize,
                             (128 * 132 + 64 * 132) * 4);
    }

    float *p_dinv, *p_g1, *p_g2, *p_Wcat;
    int *p_cnt, *p_cur, *p_rs, *p_part, *p_csr;
    cudaGetSymbolAddress((void**)&p_dinv, d_dinv);
    cudaGetSymbolAddress((void**)&p_cnt,  d_cnt);
    cudaGetSymbolAddress((void**)&p_cur,  d_cur);
    cudaGetSymbolAddress((void**)&p_rs,   d_rs);
    cudaGetSymbolAddress((void**)&p_part, d_part);
    cudaGetSymbolAddress((void**)&p_csr,  d_csr);
    cudaGetSymbolAddress((void**)&p_g1,   d_g1);
    cudaGetSymbolAddress((void**)&p_g2,   d_g2);
    cudaGetSymbolAddress((void**)&p_Wcat, d_Wcat);

    const int n  = in_sizes[0] / D_IN;   // 50000
    const int E1 = in_sizes[1] / 2;      // 600000
    const int E2 = in_sizes[2] / 2;      // 200000
    const int* src1 = ei1; const int* dst1 = ei1 + E1;
    const int* src2 = ei2; const int* dst2 = ei2 + E2;

    const int T = 256;
    const int tiles = (n + 127) / 128;        // 391
    const int nblk = (n + 1023) / 1024;       // 49
    const int smem12 = (128 * 132 + 64 * 132) * 4;   // 101376

    // ---- fork: GEMM1 runs concurrently with CSR build ----
    cudaEventRecord(evFork, 0);
    cudaStreamWaitEvent(sB, evFork, 0);
    mma_gemm1_kernel<<<tiles, 256, 0, sB>>>(x, W1, p_g1, n);
    cudaEventRecord(evJoin, sB);

    // ---- CSR build on main stream ----
    zero_wcat_kernel<<<(n + D_H * D_Z2 + T - 1) / T, T>>>(p_cnt, p_Wcat, Wmu, Wls, n);
    hist2_kernel<<<(E1 + E2 + T - 1) / T, T>>>(p_cnt, dst1, E1, dst2, E2);
    partial_kernel<<<nblk, 256>>>(p_cnt, p_part, n);
    scan_write_kernel<<<nblk, 256>>>(p_cnt, p_part, p_rs, p_cur, p_dinv, n, nblk);
    scatter2_kernel<<<(E1 + E2 + T - 1) / T, T>>>(src1, dst1, E1, src2, dst2, E2, p_cur, p_csr);

    // ---- join, then fused agg1 + GEMM2 ----
    cudaStreamWaitEvent(0, evJoin, 0);
    layer12_kernel<<<tiles, 256, smem12>>>(p_rs, p_csr, p_g1, p_dinv, b1, p_Wcat, p_g2, n);

    // ---- agg2 ----
    agg2_kernel<<<(n * 32 + T - 1) / T, T>>>(p_rs, p_csr, p_g2, p_dinv, bmu, bls, out, n);
}

// round 13
// speedup vs baseline: 1.2297x; 1.2297x over previous
#include <cuda_runtime.h>
#include <cstdint>

#define N_NODES 50000
#define D_IN    128
#define D_H     128
#define D_Z2    64
#define D_Z     32
#define MAX_E   800000

// -------- device scratch --------
__device__ __align__(16) float d_dinv[N_NODES];
__device__ __align__(16) int   d_cnt [N_NODES];       // self-zeroing: scan_write clears after read
__device__ __align__(16) int   d_cur [N_NODES + 4];
__device__ __align__(16) int   d_rs  [N_NODES + 4];
__device__ __align__(16) int   d_part[64];
__device__ __align__(16) int   d_csr [MAX_E];
__device__ __align__(16) float d_g1  [N_NODES * D_H];   // h0 = x@W1 (unscaled)
__device__ __align__(16) float d_h   [N_NODES * D_H];   // layer-1 output (must be separate from d_g1!)
__device__ __align__(16) float d_g2  [N_NODES * D_Z2];

// -------- helpers --------
__device__ __forceinline__ uint32_t tf32_hi(float x) {
    uint32_t u;
    asm("cvt.rna.tf32.f32 %0, %1;" : "=r"(u) : "f"(x));
    return u;
}
__device__ __forceinline__ void tf32_split(float x, uint32_t& hi, uint32_t& lo) {
    hi = tf32_hi(x);
    lo = tf32_hi(x - __uint_as_float(hi));
}
__device__ __forceinline__ void mma_tf32(float c[4], const uint32_t a[4], const uint32_t b[2]) {
    asm volatile(
        "mma.sync.aligned.m16n8k8.row.col.f32.tf32.tf32.f32 "
        "{%0,%1,%2,%3}, {%4,%5,%6,%7}, {%8,%9}, {%0,%1,%2,%3};"
        : "+f"(c[0]), "+f"(c[1]), "+f"(c[2]), "+f"(c[3])
        : "r"(a[0]), "r"(a[1]), "r"(a[2]), "r"(a[3]), "r"(b[0]), "r"(b[1]));
}

// -------- CSR build --------
// 4 edges per thread (E1, E2 divisible by 4; slices 16B-aligned)
__global__ void hist2_kernel(int* __restrict__ cnt,
                             const int* __restrict__ dst1, int E1,
                             const int* __restrict__ dst2, int E2) {
    int q1 = E1 >> 2, q2 = E2 >> 2;
    int i = blockIdx.x * blockDim.x + threadIdx.x;
    int4 d;
    if (i < q1)            d = *reinterpret_cast<const int4*>(dst1 + i * 4);
    else if (i < q1 + q2)  d = *reinterpret_cast<const int4*>(dst2 + (i - q1) * 4);
    else return;
    atomicAdd(&cnt[d.x], 1);
    atomicAdd(&cnt[d.y], 1);
    atomicAdd(&cnt[d.z], 1);
    atomicAdd(&cnt[d.w], 1);
}

__global__ void partial_kernel(const int* __restrict__ cnt, int* __restrict__ part, int n) {
    __shared__ int sh[256];
    int t = threadIdx.x;
    int i = blockIdx.x * 1024 + t * 4;
    int s = 0;
    if (i < n) {
        int4 v = *reinterpret_cast<const int4*>(cnt + i);
        s = v.x + v.y + v.z + v.w;
    }
    sh[t] = s;
    __syncthreads();
    for (int off = 128; off > 0; off >>= 1) {
        if (t < off) sh[t] += sh[t + off];
        __syncthreads();
    }
    if (t == 0) part[blockIdx.x] = sh[0];
}

// exclusive scan + write rs/cur/dinv; ALSO zeroes cnt for the next replay
__global__ void scan_write_kernel(int* __restrict__ cnt, const int* __restrict__ part,
                                  int* __restrict__ rs, int* __restrict__ cur,
                                  float* __restrict__ dinv, int n, int nblk) {
    __shared__ int sh[256];
    __shared__ int base_s;
    int t = threadIdx.x;
    int b = blockIdx.x;
    if (t == 0) {
        int base = 0;
        for (int j = 0; j < b; j++) base += part[j];
        base_s = base;
        if (b == 0) {
            int tot = 0;
            for (int j = 0; j < nblk; j++) tot += part[j];
            rs[n] = tot;
        }
    }
    int i = b * 1024 + t * 4;
    int4 v = make_int4(0, 0, 0, 0);
    if (i < n) v = *reinterpret_cast<const int4*>(cnt + i);
    int s = v.x + v.y + v.z + v.w;
    sh[t] = s;
    __syncthreads();
    for (int off = 1; off < 256; off <<= 1) {
        int tmp = (t >= off) ? sh[t - off] : 0;
        __syncthreads();
        sh[t] += tmp;
        __syncthreads();
    }
    int thrbase = base_s + sh[t] - s;
    if (i < n) {
        int r0 = thrbase;
        rs[i]     = r0; cur[i]     = r0; dinv[i]     = rsqrtf((float)(v.x + 1));
        int r1 = r0 + v.x;
        rs[i + 1] = r1; cur[i + 1] = r1; dinv[i + 1] = rsqrtf((float)(v.y + 1));
        int r2 = r1 + v.y;
        rs[i + 2] = r2; cur[i + 2] = r2; dinv[i + 2] = rsqrtf((float)(v.z + 1));
        int r3 = r2 + v.z;
        rs[i + 3] = r3; cur[i + 3] = r3; dinv[i + 3] = rsqrtf((float)(v.w + 1));
        *reinterpret_cast<int4*>(cnt + i) = make_int4(0, 0, 0, 0);  // ready for next replay
    }
}

__global__ void scatter2_kernel(const int* __restrict__ src1, const int* __restrict__ dst1, int E1,
                                const int* __restrict__ src2, const int* __restrict__ dst2, int E2,
                                int* __restrict__ cur, int* __restrict__ csr) {
    int q1 = E1 >> 2, q2 = E2 >> 2;
    int i = blockIdx.x * blockDim.x + threadIdx.x;
    int4 s, d;
    if (i < q1) {
        s = *reinterpret_cast<const int4*>(src1 + i * 4);
        d = *reinterpret_cast<const int4*>(dst1 + i * 4);
    } else if (i < q1 + q2) {
        s = *reinterpret_cast<const int4*>(src2 + (i - q1) * 4);
        d = *reinterpret_cast<const int4*>(dst2 + (i - q1) * 4);
    } else return;
    csr[atomicAdd(&cur[d.x], 1)] = s.x;
    csr[atomicAdd(&cur[d.y], 1)] = s.y;
    csr[atomicAdd(&cur[d.z], 1)] = s.z;
    csr[atomicAdd(&cur[d.w], 1)] = s.w;
}

// ==================== GEMM1: 3xTF32, h0 = x@W1 (unscaled) ====================
__global__ __launch_bounds__(256) void mma_gemm1_kernel(
    const float* __restrict__ X, const float* __restrict__ W,
    float* __restrict__ g, int nrows)
{
    constexpr int NOUT = 128;
    constexpr int WN = 64, NT = 8, LDA = 36;
    __shared__ float As[128 * LDA];
    __shared__ float Bs[NOUT * LDA];

    const int tid = threadIdx.x;
    const int wid = tid >> 5, lane = tid & 31;
    const int wm = wid & 3, wn = wid >> 2;
    const int row0 = blockIdx.x * 128;
    const int qid = lane >> 2, qt = lane & 3;

    float acc[2][NT][4];
#pragma unroll
    for (int mi = 0; mi < 2; mi++)
#pragma unroll
        for (int ni = 0; ni < NT; ni++)
#pragma unroll
            for (int j = 0; j < 4; j++) acc[mi][ni][j] = 0.0f;

    for (int c = 0; c < 4; c++) {
#pragma unroll
        for (int i = tid; i < 1024; i += 256) {
            int r = i >> 3, c4 = (i & 7) * 4;
            float4 v = make_float4(0.f, 0.f, 0.f, 0.f);
            if (row0 + r < nrows)
                v = *reinterpret_cast<const float4*>(X + (size_t)(row0 + r) * 128 + c * 32 + c4);
            *reinterpret_cast<float4*>(&As[r * LDA + c4]) = v;
        }
#pragma unroll
        for (int i = tid; i < NOUT * 32; i += 256) {
            int nn = i % NOUT, kk = i / NOUT;
            Bs[nn * LDA + kk] = W[(size_t)(c * 32 + kk) * NOUT + nn];
        }
        __syncthreads();

#pragma unroll
        for (int ks = 0; ks < 4; ks++) {
            uint32_t ahi[2][4], alo[2][4];
#pragma unroll
            for (int mi = 0; mi < 2; mi++) {
                int r = wm * 32 + mi * 16 + qid;
                int k = ks * 8 + qt;
                tf32_split(As[r * LDA + k],           ahi[mi][0], alo[mi][0]);
                tf32_split(As[(r + 8) * LDA + k],     ahi[mi][1], alo[mi][1]);
                tf32_split(As[r * LDA + k + 4],       ahi[mi][2], alo[mi][2]);
                tf32_split(As[(r + 8) * LDA + k + 4], ahi[mi][3], alo[mi][3]);
            }
#pragma unroll
            for (int ni = 0; ni < NT; ni++) {
                int nn = wn * WN + ni * 8 + qid;
                int k = ks * 8 + qt;
                uint32_t bhi[2], blo[2];
                tf32_split(Bs[nn * LDA + k],     bhi[0], blo[0]);
                tf32_split(Bs[nn * LDA + k + 4], bhi[1], blo[1]);
#pragma unroll
                for (int mi = 0; mi < 2; mi++) {
                    mma_tf32(acc[mi][ni], ahi[mi], blo);
                    mma_tf32(acc[mi][ni], alo[mi], bhi);
                    mma_tf32(acc[mi][ni], ahi[mi], bhi);
                }
            }
        }
        __syncthreads();
    }

#pragma unroll
    for (int mi = 0; mi < 2; mi++) {
        int r0 = row0 + wm * 32 + mi * 16 + qid;
        int r1 = r0 + 8;
#pragma unroll
        for (int ni = 0; ni < NT; ni++) {
            int col = wn * WN + ni * 8 + qt * 2;
            if (r0 < nrows) {
                float2 o = make_float2(acc[mi][ni][0], acc[mi][ni][1]);
                *reinterpret_cast<float2*>(g + (size_t)r0 * NOUT + col) = o;
            }
            if (r1 < nrows) {
                float2 o = make_float2(acc[mi][ni][2], acc[mi][ni][3]);
                *reinterpret_cast<float2*>(g + (size_t)r1 * NOUT + col) = o;
            }
        }
    }
}

// ==================== GEMM2: 3xTF32, g2 = (h@[Wmu|Wls]) * dinv ====================
// B loaded directly from Wmu/Wls (no Wcat materialization).
__global__ __launch_bounds__(256) void mma_gemm2_kernel(
    const float* __restrict__ X, const float* __restrict__ Wmu, const float* __restrict__ Wls,
    const float* __restrict__ dinv, float* __restrict__ g, int nrows)
{
    constexpr int NOUT = 64;
    constexpr int WN = 32, NT = 4, LDA = 36;
    __shared__ float As[128 * LDA];
    __shared__ float Bs[NOUT * LDA];

    const int tid = threadIdx.x;
    const int wid = tid >> 5, lane = tid & 31;
    const int wm = wid & 3, wn = wid >> 2;
    const int row0 = blockIdx.x * 128;
    const int qid = lane >> 2, qt = lane & 3;

    float acc[2][NT][4];
#pragma unroll
    for (int mi = 0; mi < 2; mi++)
#pragma unroll
        for (int ni = 0; ni < NT; ni++)
#pragma unroll
            for (int j = 0; j < 4; j++) acc[mi][ni][j] = 0.0f;

    for (int c = 0; c < 4; c++) {
#pragma unroll
        for (int i = tid; i < 1024; i += 256) {
            int r = i >> 3, c4 = (i & 7) * 4;
            float4 v = make_float4(0.f, 0.f, 0.f, 0.f);
            if (row0 + r < nrows)
                v = *reinterpret_cast<const float4*>(X + (size_t)(row0 + r) * 128 + c * 32 + c4);
            *reinterpret_cast<float4*>(&As[r * LDA + c4]) = v;
        }
#pragma unroll
        for (int i = tid; i < NOUT * 32; i += 256) {
            int nn = i % NOUT, kk = i / NOUT;
            int krow = c * 32 + kk;
            Bs[nn * LDA + kk] = (nn < D_Z) ? Wmu[(size_t)krow * D_Z + nn]
                                           : Wls[(size_t)krow * D_Z + (nn - D_Z)];
        }
        __syncthreads();

#pragma unroll
        for (int ks = 0; ks < 4; ks++) {
            uint32_t ahi[2][4], alo[2][4];
#pragma unroll
            for (int mi = 0; mi < 2; mi++) {
                int r = wm * 32 + mi * 16 + qid;
                int k = ks * 8 + qt;
                tf32_split(As[r * LDA + k],           ahi[mi][0], alo[mi][0]);
                tf32_split(As[(r + 8) * LDA + k],     ahi[mi][1], alo[mi][1]);
                tf32_split(As[r * LDA + k + 4],       ahi[mi][2], alo[mi][2]);
                tf32_split(As[(r + 8) * LDA + k + 4], ahi[mi][3], alo[mi][3]);
            }
#pragma unroll
            for (int ni = 0; ni < NT; ni++) {
                int nn = wn * WN + ni * 8 + qid;
                int k = ks * 8 + qt;
                uint32_t bhi[2], blo[2];
                tf32_split(Bs[nn * LDA + k],     bhi[0], blo[0]);
                tf32_split(Bs[nn * LDA + k + 4], bhi[1], blo[1]);
#pragma unroll
                for (int mi = 0; mi < 2; mi++) {
                    mma_tf32(acc[mi][ni], ahi[mi], blo);
                    mma_tf32(acc[mi][ni], alo[mi], bhi);
                    mma_tf32(acc[mi][ni], ahi[mi], bhi);
                }
            }
        }
        __syncthreads();
    }

#pragma unroll
    for (int mi = 0; mi < 2; mi++) {
        int r0 = row0 + wm * 32 + mi * 16 + qid;
        int r1 = r0 + 8;
        float w0 = (r0 < nrows) ? dinv[r0] : 0.f;
        float w1 = (r1 < nrows) ? dinv[r1] : 0.f;
#pragma unroll
        for (int ni = 0; ni < NT; ni++) {
            int col = wn * WN + ni * 8 + qt * 2;
            if (r0 < nrows) {
                float2 o = make_float2(acc[mi][ni][0] * w0, acc[mi][ni][1] * w0);
                *reinterpret_cast<float2*>(g + (size_t)r0 * NOUT + col) = o;
            }
            if (r1 < nrows) {
                float2 o = make_float2(acc[mi][ni][2] * w1, acc[mi][ni][3] * w1);
                *reinterpret_cast<float2*>(g + (size_t)r1 * NOUT + col) = o;
            }
        }
    }
}

// -------- agg1 (F=128): h[d] = relu( wd*(sum_s dinv[s]*h0[s] + wd*h0[d]) + b ) --------
__global__ __launch_bounds__(256) void agg1_kernel(
    const int* __restrict__ rs, const int* __restrict__ csr,
    const float* __restrict__ h0, const float* __restrict__ dinv,
    const float* __restrict__ b1, float* __restrict__ h, int n)
{
    int d = (blockIdx.x * blockDim.x + threadIdx.x) >> 5;
    int lane = threadIdx.x & 31;
    if (d >= n) return;

    const float4* gv = reinterpret_cast<const float4*>(h0);
    float wd = dinv[d];
    float4 sv = gv[(size_t)d * 32 + lane];
    float4 a0 = make_float4(sv.x * wd, sv.y * wd, sv.z * wd, sv.w * wd);
    float4 a1 = make_float4(0.f, 0.f, 0.f, 0.f);
    float4 a2 = make_float4(0.f, 0.f, 0.f, 0.f);
    float4 a3 = make_float4(0.f, 0.f, 0.f, 0.f);

    int e = rs[d], end = rs[d + 1];
    for (; e + 4 <= end; e += 4) {
        int s0 = __ldg(&csr[e]);
        int s1 = __ldg(&csr[e + 1]);
        int s2 = __ldg(&csr[e + 2]);
        int s3 = __ldg(&csr[e + 3]);
        float w0 = __ldg(&dinv[s0]);
        float w1 = __ldg(&dinv[s1]);
        float w2 = __ldg(&dinv[s2]);
        float w3 = __ldg(&dinv[s3]);
        float4 v0 = gv[(size_t)s0 * 32 + lane];
        float4 v1 = gv[(size_t)s1 * 32 + lane];
        float4 v2 = gv[(size_t)s2 * 32 + lane];
        float4 v3 = gv[(size_t)s3 * 32 + lane];
        a0.x = fmaf(v0.x, w0, a0.x); a0.y = fmaf(v0.y, w0, a0.y);
        a0.z = fmaf(v0.z, w0, a0.z); a0.w = fmaf(v0.w, w0, a0.w);
        a1.x = fmaf(v1.x, w1, a1.x); a1.y = fmaf(v1.y, w1, a1.y);
        a1.z = fmaf(v1.z, w1, a1.z); a1.w = fmaf(v1.w, w1, a1.w);
        a2.x = fmaf(v2.x, w2, a2.x); a2.y = fmaf(v2.y, w2, a2.y);
        a2.z = fmaf(v2.z, w2, a2.z); a2.w = fmaf(v2.w, w2, a2.w);
        a3.x = fmaf(v3.x, w3, a3.x); a3.y = fmaf(v3.y, w3, a3.y);
        a3.z = fmaf(v3.z, w3, a3.z); a3.w = fmaf(v3.w, w3, a3.w);
    }
    for (; e < end; e++) {
        int s0 = __ldg(&csr[e]);
        float w0 = __ldg(&dinv[s0]);
        float4 v0 = gv[(size_t)s0 * 32 + lane];
        a0.x = fmaf(v0.x, w0, a0.x); a0.y = fmaf(v0.y, w0, a0.y);
        a0.z = fmaf(v0.z, w0, a0.z); a0.w = fmaf(v0.w, w0, a0.w);
    }
    float4 bb = reinterpret_cast<const float4*>(b1)[lane];
    float sx = (a0.x + a1.x) + (a2.x + a3.x);
    float sy = (a0.y + a1.y) + (a2.y + a3.y);
    float sz = (a0.z + a1.z) + (a2.z + a3.z);
    float sw = (a0.w + a1.w) + (a2.w + a3.w);
    float4 r;
    r.x = fmaxf(fmaf(sx, wd, bb.x), 0.f);
    r.y = fmaxf(fmaf(sy, wd, bb.y), 0.f);
    r.z = fmaxf(fmaf(sz, wd, bb.z), 0.f);
    r.w = fmaxf(fmaf(sw, wd, bb.w), 0.f);
    reinterpret_cast<float4*>(h)[(size_t)d * 32 + lane] = r;
}

// -------- agg2 (F=64): fused bias + mu/logstd split --------
__global__ __launch_bounds__(256) void agg2_kernel(
    const int* __restrict__ rs, const int* __restrict__ csr,
    const float* __restrict__ g, const float* __restrict__ dinv,
    const float* __restrict__ bmu, const float* __restrict__ bls,
    float* __restrict__ out, int n)
{
    int d = (blockIdx.x * blockDim.x + threadIdx.x) >> 5;
    int lane = threadIdx.x & 31;
    if (d >= n) return;

    const float2* gv = reinterpret_cast<const float2*>(g);
    float2 a0 = gv[(size_t)d * 32 + lane];
    float2 a1 = make_float2(0.f, 0.f);
    float2 a2 = make_float2(0.f, 0.f);
    float2 a3 = make_float2(0.f, 0.f);

    int e = rs[d], end = rs[d + 1];
    for (; e + 4 <= end; e += 4) {
        int s0 = __ldg(&csr[e]);
        int s1 = __ldg(&csr[e + 1]);
        int s2 = __ldg(&csr[e + 2]);
        int s3 = __ldg(&csr[e + 3]);
        float2 v0 = gv[(size_t)s0 * 32 + lane];
        float2 v1 = gv[(size_t)s1 * 32 + lane];
        float2 v2 = gv[(size_t)s2 * 32 + lane];
        float2 v3 = gv[(size_t)s3 * 32 + lane];
        a0.x += v0.x; a0.y += v0.y;
        a1.x += v1.x; a1.y += v1.y;
        a2.x += v2.x; a2.y += v2.y;
        a3.x += v3.x; a3.y += v3.y;
    }
    for (; e < end; e++) {
        int s0 = __ldg(&csr[e]);
        float2 v0 = gv[(size_t)s0 * 32 + lane];
        a0.x += v0.x; a0.y += v0.y;
    }
    float w = dinv[d];
    float vx = ((a0.x + a1.x) + (a2.x + a3.x)) * w;
    float vy = ((a0.y + a1.y) + (a2.y + a3.y)) * w;
    int c0 = lane * 2, c1 = lane * 2 + 1;
    if (c0 < D_Z) {
        float2 o = make_float2(vx + bmu[c0], vy + bmu[c1]);
        reinterpret_cast<float2*>(out)[(size_t)d * 16 + lane] = o;
    } else {
        float2 o = make_float2(vx + bls[c0 - D_Z], vy + bls[c1 - D_Z]);
        reinterpret_cast<float2*>(out + (size_t)n * D_Z)[(size_t)d * 16 + (lane - 16)] = o;
    }
}

extern "C" void kernel_launch(void* const* d_in, const int* in_sizes, int n_in,
                              void* d_out, int out_size)
{
    const float* x    = (const float*)d_in[0];
    const int*   ei1  = (const int*)d_in[1];
    const int*   ei2  = (const int*)d_in[2];
    const float* W1   = (const float*)d_in[3];
    const float* b1   = (const float*)d_in[4];
    const float* Wmu  = (const float*)d_in[5];
    const float* bmu  = (const float*)d_in[6];
    const float* Wls  = (const float*)d_in[7];
    const float* bls  = (const float*)d_in[8];
    float* out = (float*)d_out;

    static cudaStream_t sB = nullptr;
    static cudaEvent_t evFork = nullptr, evJoin = nullptr;
    if (sB == nullptr) {
        cudaStreamCreateWithFlags(&sB, cudaStreamNonBlocking);
        cudaEventCreateWithFlags(&evFork, cudaEventDisableTiming);
        cudaEventCreateWithFlags(&evJoin, cudaEventDisableTiming);
    }

    float *p_dinv, *p_g1, *p_h, *p_g2;
    int *p_cnt, *p_cur, *p_rs, *p_part, *p_csr;
    cudaGetSymbolAddress((void**)&p_dinv, d_dinv);
    cudaGetSymbolAddress((void**)&p_cnt,  d_cnt);
    cudaGetSymbolAddress((void**)&p_cur,  d_cur);
    cudaGetSymbolAddress((void**)&p_rs,   d_rs);
    cudaGetSymbolAddress((void**)&p_part, d_part);
    cudaGetSymbolAddress((void**)&p_csr,  d_csr);
    cudaGetSymbolAddress((void**)&p_g1,   d_g1);
    cudaGetSymbolAddress((void**)&p_h,    d_h);
    cudaGetSymbolAddress((void**)&p_g2,   d_g2);

    const int n  = in_sizes[0] / D_IN;   // 50000
    const int E1 = in_sizes[1] / 2;      // 600000
    const int E2 = in_sizes[2] / 2;      // 200000
    const int* src1 = ei1; const int* dst1 = ei1 + E1;
    const int* src2 = ei2; const int* dst2 = ei2 + E2;

    const int T = 256;
    const int tiles = (n + 127) / 128;        // 391
    const int nblk = (n + 1023) / 1024;       // 49
    const int nq = (E1 >> 2) + (E2 >> 2);     // 200000 threads (4 edges each)

    // ---- fork: GEMM1 concurrent with CSR build (cnt pre-zeroed by last replay / BSS) ----
    cudaEventRecord(evFork, 0);
    cudaStreamWaitEvent(sB, evFork, 0);
    mma_gemm1_kernel<<<tiles, 256, 0, sB>>>(x, W1, p_g1, n);
    cudaEventRecord(evJoin, sB);

    // ---- CSR build on main stream ----
    hist2_kernel<<<(nq + T - 1) / T, T>>>(p_cnt, dst1, E1, dst2, E2);
    partial_kernel<<<nblk, 256>>>(p_cnt, p_part, n);
    scan_write_kernel<<<nblk, 256>>>(p_cnt, p_part, p_rs, p_cur, p_dinv, n, nblk);
    scatter2_kernel<<<(nq + T - 1) / T, T>>>(src1, dst1, E1, src2, dst2, E2, p_cur, p_csr);

    // ---- join, then layer-1 aggregation (h0 -> separate d_h buffer) ----
    cudaStreamWaitEvent(0, evJoin, 0);
    agg1_kernel<<<(n * 32 + T - 1) / T, T>>>(p_rs, p_csr, p_g1, p_dinv, b1, p_h, n);

    // ---- layer 2 (fused heads, B direct from Wmu/Wls) ----
    mma_gemm2_kernel<<<tiles, 256>>>(p_h, Wmu, Wls, p_dinv, p_g2, n);
    agg2_kernel<<<(n * 32 + T - 1) / T, T>>>(p_rs, p_csr, p_g2, p_dinv, bmu, bls, out, n);
}

// round 14
// speedup vs baseline: 1.2327x; 1.0024x over previous
#include <cuda_runtime.h>
#include <cuda_fp16.h>
#include <cstdint>

#define N_NODES 50000
#define D_IN    128
#define D_H     128
#define D_Z2    64
#define D_Z     32
#define MAX_E   800000

// -------- device scratch --------
__device__ __align__(16) float  d_dinv[N_NODES];
__device__ __align__(16) int    d_cnt [N_NODES];      // self-zeroing
__device__ __align__(16) int    d_cur [N_NODES + 4];
__device__ __align__(16) int    d_rs  [N_NODES + 4];
__device__ __align__(16) int    d_part[64];
__device__ __align__(16) int    d_csr [MAX_E];
__device__ __align__(16) __half d_g1  [N_NODES * D_H];   // h0 = x@W1, fp16 gather source
__device__ __align__(16) float  d_h   [N_NODES * D_H];   // layer-1 output (fp32, feeds GEMM2)
__device__ __align__(16) __half d_g2  [N_NODES * D_Z2];  // (h@[Wmu|Wls])*dinv, fp16 gather source

// -------- helpers --------
__device__ __forceinline__ uint32_t tf32_hi(float x) {
    uint32_t u;
    asm("cvt.rna.tf32.f32 %0, %1;" : "=r"(u) : "f"(x));
    return u;
}
__device__ __forceinline__ void tf32_split(float x, uint32_t& hi, uint32_t& lo) {
    hi = tf32_hi(x);
    lo = tf32_hi(x - __uint_as_float(hi));
}
__device__ __forceinline__ void mma_tf32(float c[4], const uint32_t a[4], const uint32_t b[2]) {
    asm volatile(
        "mma.sync.aligned.m16n8k8.row.col.f32.tf32.tf32.f32 "
        "{%0,%1,%2,%3}, {%4,%5,%6,%7}, {%8,%9}, {%0,%1,%2,%3};"
        : "+f"(c[0]), "+f"(c[1]), "+f"(c[2]), "+f"(c[3])
        : "r"(a[0]), "r"(a[1]), "r"(a[2]), "r"(a[3]), "r"(b[0]), "r"(b[1]));
}
__device__ __forceinline__ float4 h4_to_f4(uint2 v) {
    float2 fa = __half22float2(*reinterpret_cast<__half2*>(&v.x));
    float2 fb = __half22float2(*reinterpret_cast<__half2*>(&v.y));
    return make_float4(fa.x, fa.y, fb.x, fb.y);
}

// -------- CSR build --------
__global__ void hist2_kernel(int* __restrict__ cnt,
                             const int* __restrict__ dst1, int E1,
                             const int* __restrict__ dst2, int E2) {
    int q1 = E1 >> 2, q2 = E2 >> 2;
    int i = blockIdx.x * blockDim.x + threadIdx.x;
    int4 d;
    if (i < q1)            d = *reinterpret_cast<const int4*>(dst1 + i * 4);
    else if (i < q1 + q2)  d = *reinterpret_cast<const int4*>(dst2 + (i - q1) * 4);
    else return;
    atomicAdd(&cnt[d.x], 1);
    atomicAdd(&cnt[d.y], 1);
    atomicAdd(&cnt[d.z], 1);
    atomicAdd(&cnt[d.w], 1);
}

__global__ void partial_kernel(const int* __restrict__ cnt, int* __restrict__ part, int n) {
    __shared__ int sh[256];
    int t = threadIdx.x;
    int i = blockIdx.x * 1024 + t * 4;
    int s = 0;
    if (i < n) {
        int4 v = *reinterpret_cast<const int4*>(cnt + i);
        s = v.x + v.y + v.z + v.w;
    }
    sh[t] = s;
    __syncthreads();
    for (int off = 128; off > 0; off >>= 1) {
        if (t < off) sh[t] += sh[t + off];
        __syncthreads();
    }
    if (t == 0) part[blockIdx.x] = sh[0];
}

__global__ void scan_write_kernel(int* __restrict__ cnt, const int* __restrict__ part,
                                  int* __restrict__ rs, int* __restrict__ cur,
                                  float* __restrict__ dinv, int n, int nblk) {
    __shared__ int sh[256];
    __shared__ int base_s;
    int t = threadIdx.x;
    int b = blockIdx.x;
    if (t == 0) {
        int base = 0;
        for (int j = 0; j < b; j++) base += part[j];
        base_s = base;
        if (b == 0) {
            int tot = 0;
            for (int j = 0; j < nblk; j++) tot += part[j];
            rs[n] = tot;
        }
    }
    int i = b * 1024 + t * 4;
    int4 v = make_int4(0, 0, 0, 0);
    if (i < n) v = *reinterpret_cast<const int4*>(cnt + i);
    int s = v.x + v.y + v.z + v.w;
    sh[t] = s;
    __syncthreads();
    for (int off = 1; off < 256; off <<= 1) {
        int tmp = (t >= off) ? sh[t - off] : 0;
        __syncthreads();
        sh[t] += tmp;
        __syncthreads();
    }
    int thrbase = base_s + sh[t] - s;
    if (i < n) {
        int r0 = thrbase;
        rs[i]     = r0; cur[i]     = r0; dinv[i]     = rsqrtf((float)(v.x + 1));
        int r1 = r0 + v.x;
        rs[i + 1] = r1; cur[i + 1] = r1; dinv[i + 1] = rsqrtf((float)(v.y + 1));
        int r2 = r1 + v.y;
        rs[i + 2] = r2; cur[i + 2] = r2; dinv[i + 2] = rsqrtf((float)(v.z + 1));
        int r3 = r2 + v.z;
        rs[i + 3] = r3; cur[i + 3] = r3; dinv[i + 3] = rsqrtf((float)(v.w + 1));
        *reinterpret_cast<int4*>(cnt + i) = make_int4(0, 0, 0, 0);
    }
}

__global__ void scatter2_kernel(const int* __restrict__ src1, const int* __restrict__ dst1, int E1,
                                const int* __restrict__ src2, const int* __restrict__ dst2, int E2,
                                int* __restrict__ cur, int* __restrict__ csr) {
    int q1 = E1 >> 2, q2 = E2 >> 2;
    int i = blockIdx.x * blockDim.x + threadIdx.x;
    int4 s, d;
    if (i < q1) {
        s = *reinterpret_cast<const int4*>(src1 + i * 4);
        d = *reinterpret_cast<const int4*>(dst1 + i * 4);
    } else if (i < q1 + q2) {
        s = *reinterpret_cast<const int4*>(src2 + (i - q1) * 4);
        d = *reinterpret_cast<const int4*>(dst2 + (i - q1) * 4);
    } else return;
    csr[atomicAdd(&cur[d.x], 1)] = s.x;
    csr[atomicAdd(&cur[d.y], 1)] = s.y;
    csr[atomicAdd(&cur[d.z], 1)] = s.z;
    csr[atomicAdd(&cur[d.w], 1)] = s.w;
}

// ==================== GEMM1: 3xTF32, h0 = x@W1 -> fp16 ====================
__global__ __launch_bounds__(256) void mma_gemm1_kernel(
    const float* __restrict__ X, const float* __restrict__ W,
    __half* __restrict__ g, int nrows)
{
    constexpr int NOUT = 128;
    constexpr int WN = 64, NT = 8, LDA = 36;
    __shared__ float As[128 * LDA];
    __shared__ float Bs[NOUT * LDA];

    const int tid = threadIdx.x;
    const int wid = tid >> 5, lane = tid & 31;
    const int wm = wid & 3, wn = wid >> 2;
    const int row0 = blockIdx.x * 128;
    const int qid = lane >> 2, qt = lane & 3;

    float acc[2][NT][4];
#pragma unroll
    for (int mi = 0; mi < 2; mi++)
#pragma unroll
        for (int ni = 0; ni < NT; ni++)
#pragma unroll
            for (int j = 0; j < 4; j++) acc[mi][ni][j] = 0.0f;

    for (int c = 0; c < 4; c++) {
#pragma unroll
        for (int i = tid; i < 1024; i += 256) {
            int r = i >> 3, c4 = (i & 7) * 4;
            float4 v = make_float4(0.f, 0.f, 0.f, 0.f);
            if (row0 + r < nrows)
                v = *reinterpret_cast<const float4*>(X + (size_t)(row0 + r) * 128 + c * 32 + c4);
            *reinterpret_cast<float4*>(&As[r * LDA + c4]) = v;
        }
#pragma unroll
        for (int i = tid; i < NOUT * 32; i += 256) {
            int nn = i % NOUT, kk = i / NOUT;
            Bs[nn * LDA + kk] = W[(size_t)(c * 32 + kk) * NOUT + nn];
        }
        __syncthreads();

#pragma unroll
        for (int ks = 0; ks < 4; ks++) {
            uint32_t ahi[2][4], alo[2][4];
#pragma unroll
            for (int mi = 0; mi < 2; mi++) {
                int r = wm * 32 + mi * 16 + qid;
                int k = ks * 8 + qt;
                tf32_split(As[r * LDA + k],           ahi[mi][0], alo[mi][0]);
                tf32_split(As[(r + 8) * LDA + k],     ahi[mi][1], alo[mi][1]);
                tf32_split(As[r * LDA + k + 4],       ahi[mi][2], alo[mi][2]);
                tf32_split(As[(r + 8) * LDA + k + 4], ahi[mi][3], alo[mi][3]);
            }
#pragma unroll
            for (int ni = 0; ni < NT; ni++) {
                int nn = wn * WN + ni * 8 + qid;
                int k = ks * 8 + qt;
                uint32_t bhi[2], blo[2];
                tf32_split(Bs[nn * LDA + k],     bhi[0], blo[0]);
                tf32_split(Bs[nn * LDA + k + 4], bhi[1], blo[1]);
#pragma unroll
                for (int mi = 0; mi < 2; mi++) {
                    mma_tf32(acc[mi][ni], ahi[mi], blo);
                    mma_tf32(acc[mi][ni], alo[mi], bhi);
                    mma_tf32(acc[mi][ni], ahi[mi], bhi);
                }
            }
        }
        __syncthreads();
    }

#pragma unroll
    for (int mi = 0; mi < 2; mi++) {
        int r0 = row0 + wm * 32 + mi * 16 + qid;
        int r1 = r0 + 8;
#pragma unroll
        for (int ni = 0; ni < NT; ni++) {
            int col = wn * WN + ni * 8 + qt * 2;   // even
            if (r0 < nrows)
                *reinterpret_cast<__half2*>(g + (size_t)r0 * NOUT + col) =
                    __floats2half2_rn(acc[mi][ni][0], acc[mi][ni][1]);
            if (r1 < nrows)
                *reinterpret_cast<__half2*>(g + (size_t)r1 * NOUT + col) =
                    __floats2half2_rn(acc[mi][ni][2], acc[mi][ni][3]);
        }
    }
}

// ==================== GEMM2: 3xTF32, g2 = (h@[Wmu|Wls]) * dinv -> fp16 ====================
__global__ __launch_bounds__(256) void mma_gemm2_kernel(
    const float* __restrict__ X, const float* __restrict__ Wmu, const float* __restrict__ Wls,
    const float* __restrict__ dinv, __half* __restrict__ g, int nrows)
{
    constexpr int NOUT = 64;
    constexpr int WN = 32, NT = 4, LDA = 36;
    __shared__ float As[128 * LDA];
    __shared__ float Bs[NOUT * LDA];

    const int tid = threadIdx.x;
    const int wid = tid >> 5, lane = tid & 31;
    const int wm = wid & 3, wn = wid >> 2;
    const int row0 = blockIdx.x * 128;
    const int qid = lane >> 2, qt = lane & 3;

    float acc[2][NT][4];
#pragma unroll
    for (int mi = 0; mi < 2; mi++)
#pragma unroll
        for (int ni = 0; ni < NT; ni++)
#pragma unroll
            for (int j = 0; j < 4; j++) acc[mi][ni][j] = 0.0f;

    for (int c = 0; c < 4; c++) {
#pragma unroll
        for (int i = tid; i < 1024; i += 256) {
            int r = i >> 3, c4 = (i & 7) * 4;
            float4 v = make_float4(0.f, 0.f, 0.f, 0.f);
            if (row0 + r < nrows)
                v = *reinterpret_cast<const float4*>(X + (size_t)(row0 + r) * 128 + c * 32 + c4);
            *reinterpret_cast<float4*>(&As[r * LDA + c4]) = v;
        }
#pragma unroll
        for (int i = tid; i < NOUT * 32; i += 256) {
            int nn = i % NOUT, kk = i / NOUT;
            int krow = c * 32 + kk;
            Bs[nn * LDA + kk] = (nn < D_Z) ? Wmu[(size_t)krow * D_Z + nn]
                                           : Wls[(size_t)krow * D_Z + (nn - D_Z)];
        }
        __syncthreads();

#pragma unroll
        for (int ks = 0; ks < 4; ks++) {
            uint32_t ahi[2][4], alo[2][4];
#pragma unroll
            for (int mi = 0; mi < 2; mi++) {
                int r = wm * 32 + mi * 16 + qid;
                int k = ks * 8 + qt;
                tf32_split(As[r * LDA + k],           ahi[mi][0], alo[mi][0]);
                tf32_split(As[(r + 8) * LDA + k],     ahi[mi][1], alo[mi][1]);
                tf32_split(As[r * LDA + k + 4],       ahi[mi][2], alo[mi][2]);
                tf32_split(As[(r + 8) * LDA + k + 4], ahi[mi][3], alo[mi][3]);
            }
#pragma unroll
            for (int ni = 0; ni < NT; ni++) {
                int nn = wn * WN + ni * 8 + qid;
                int k = ks * 8 + qt;
                uint32_t bhi[2], blo[2];
                tf32_split(Bs[nn * LDA + k],     bhi[0], blo[0]);
                tf32_split(Bs[nn * LDA + k + 4], bhi[1], blo[1]);
#pragma unroll
                for (int mi = 0; mi < 2; mi++) {
                    mma_tf32(acc[mi][ni], ahi[mi], blo);
                    mma_tf32(acc[mi][ni], alo[mi], bhi);
                    mma_tf32(acc[mi][ni], ahi[mi], bhi);
                }
            }
        }
        __syncthreads();
    }

#pragma unroll
    for (int mi = 0; mi < 2; mi++) {
        int r0 = row0 + wm * 32 + mi * 16 + qid;
        int r1 = r0 + 8;
        float w0 = (r0 < nrows) ? dinv[r0] : 0.f;
        float w1 = (r1 < nrows) ? dinv[r1] : 0.f;
#pragma unroll
        for (int ni = 0; ni < NT; ni++) {
            int col = wn * WN + ni * 8 + qt * 2;   // even
            if (r0 < nrows)
                *reinterpret_cast<__half2*>(g + (size_t)r0 * NOUT + col) =
                    __floats2half2_rn(acc[mi][ni][0] * w0, acc[mi][ni][1] * w0);
            if (r1 < nrows)
                *reinterpret_cast<__half2*>(g + (size_t)r1 * NOUT + col) =
                    __floats2half2_rn(acc[mi][ni][2] * w1, acc[mi][ni][3] * w1);
        }
    }
}

// -------- agg1 (F=128, fp16 source): h[d] = relu( wd*(Σ dinv[s]*h0[s] + wd*h0[d]) + b ) --------
__global__ __launch_bounds__(256) void agg1_kernel(
    const int* __restrict__ rs, const int* __restrict__ csr,
    const __half* __restrict__ h0, const float* __restrict__ dinv,
    const float* __restrict__ b1, float* __restrict__ h, int n)
{
    int d = (blockIdx.x * blockDim.x + threadIdx.x) >> 5;
    int lane = threadIdx.x & 31;
    if (d >= n) return;

    const uint2* gv = reinterpret_cast<const uint2*>(h0);   // 4 halfs per lane
    float wd = dinv[d];
    float4 sv = h4_to_f4(gv[(size_t)d * 32 + lane]);
    float4 a0 = make_float4(sv.x * wd, sv.y * wd, sv.z * wd, sv.w * wd);
    float4 a1 = make_float4(0.f, 0.f, 0.f, 0.f);
    float4 a2 = make_float4(0.f, 0.f, 0.f, 0.f);
    float4 a3 = make_float4(0.f, 0.f, 0.f, 0.f);

    int e = rs[d], end = rs[d + 1];
    for (; e + 4 <= end; e += 4) {
        int s0 = __ldg(&csr[e]);
        int s1 = __ldg(&csr[e + 1]);
        int s2 = __ldg(&csr[e + 2]);
        int s3 = __ldg(&csr[e + 3]);
        float w0 = __ldg(&dinv[s0]);
        float w1 = __ldg(&dinv[s1]);
        float w2 = __ldg(&dinv[s2]);
        float w3 = __ldg(&dinv[s3]);
        float4 v0 = h4_to_f4(gv[(size_t)s0 * 32 + lane]);
        float4 v1 = h4_to_f4(gv[(size_t)s1 * 32 + lane]);
        float4 v2 = h4_to_f4(gv[(size_t)s2 * 32 + lane]);
        float4 v3 = h4_to_f4(gv[(size_t)s3 * 32 + lane]);
        a0.x = fmaf(v0.x, w0, a0.x); a0.y = fmaf(v0.y, w0, a0.y);
        a0.z = fmaf(v0.z, w0, a0.z); a0.w = fmaf(v0.w, w0, a0.w);
        a1.x = fmaf(v1.x, w1, a1.x); a1.y = fmaf(v1.y, w1, a1.y);
        a1.z = fmaf(v1.z, w1, a1.z); a1.w = fmaf(v1.w, w1, a1.w);
        a2.x = fmaf(v2.x, w2, a2.x); a2.y = fmaf(v2.y, w2, a2.y);
        a2.z = fmaf(v2.z, w2, a2.z); a2.w = fmaf(v2.w, w2, a2.w);
        a3.x = fmaf(v3.x, w3, a3.x); a3.y = fmaf(v3.y, w3, a3.y);
        a3.z = fmaf(v3.z, w3, a3.z); a3.w = fmaf(v3.w, w3, a3.w);
    }
    for (; e < end; e++) {
        int s0 = __ldg(&csr[e]);
        float w0 = __ldg(&dinv[s0]);
        float4 v0 = h4_to_f4(gv[(size_t)s0 * 32 + lane]);
        a0.x = fmaf(v0.x, w0, a0.x); a0.y = fmaf(v0.y, w0, a0.y);
        a0.z = fmaf(v0.z, w0, a0.z); a0.w = fmaf(v0.w, w0, a0.w);
    }
    float4 bb = reinterpret_cast<const float4*>(b1)[lane];
    float sx = (a0.x + a1.x) + (a2.x + a3.x);
    float sy = (a0.y + a1.y) + (a2.y + a3.y);
    float sz = (a0.z + a1.z) + (a2.z + a3.z);
    float sw = (a0.w + a1.w) + (a2.w + a3.w);
    float4 r;
    r.x = fmaxf(fmaf(sx, wd, bb.x), 0.f);
    r.y = fmaxf(fmaf(sy, wd, bb.y), 0.f);
    r.z = fmaxf(fmaf(sz, wd, bb.z), 0.f);
    r.w = fmaxf(fmaf(sw, wd, bb.w), 0.f);
    reinterpret_cast<float4*>(h)[(size_t)d * 32 + lane] = r;
}

// -------- agg2 (F=64, fp16 source): fused bias + mu/logstd split --------
__global__ __launch_bounds__(256) void agg2_kernel(
    const int* __restrict__ rs, const int* __restrict__ csr,
    const __half* __restrict__ g, const float* __restrict__ dinv,
    const float* __restrict__ bmu, const float* __restrict__ bls,
    float* __restrict__ out, int n)
{
    int d = (blockIdx.x * blockDim.x + threadIdx.x) >> 5;
    int lane = threadIdx.x & 31;
    if (d >= n) return;

    const __half2* gv = reinterpret_cast<const __half2*>(g);   // 2 halfs per lane
    float2 s0v = __half22float2(gv[(size_t)d * 32 + lane]);
    float2 a0 = s0v;
    float2 a1 = make_float2(0.f, 0.f);
    float2 a2 = make_float2(0.f, 0.f);
    float2 a3 = make_float2(0.f, 0.f);

    int e = rs[d], end = rs[d + 1];
    for (; e + 4 <= end; e += 4) {
        int s0 = __ldg(&csr[e]);
        int s1 = __ldg(&csr[e + 1]);
        int s2 = __ldg(&csr[e + 2]);
        int s3 = __ldg(&csr[e + 3]);
        float2 v0 = __half22float2(gv[(size_t)s0 * 32 + lane]);
        float2 v1 = __half22float2(gv[(size_t)s1 * 32 + lane]);
        float2 v2 = __half22float2(gv[(size_t)s2 * 32 + lane]);
        float2 v3 = __half22float2(gv[(size_t)s3 * 32 + lane]);
        a0.x += v0.x; a0.y += v0.y;
        a1.x += v1.x; a1.y += v1.y;
        a2.x += v2.x; a2.y += v2.y;
        a3.x += v3.x; a3.y += v3.y;
    }
    for (; e < end; e++) {
        int s0 = __ldg(&csr[e]);
        float2 v0 = __half22float2(gv[(size_t)s0 * 32 + lane]);
        a0.x += v0.x; a0.y += v0.y;
    }
    float w = dinv[d];
    float vx = ((a0.x + a1.x) + (a2.x + a3.x)) * w;
    float vy = ((a0.y + a1.y) + (a2.y + a3.y)) * w;
    int c0 = lane * 2, c1 = lane * 2 + 1;
    if (c0 < D_Z) {
        float2 o = make_float2(vx + bmu[c0], vy + bmu[c1]);
        reinterpret_cast<float2*>(out)[(size_t)d * 16 + lane] = o;
    } else {
        float2 o = make_float2(vx + bls[c0 - D_Z], vy + bls[c1 - D_Z]);
        reinterpret_cast<float2*>(out + (size_t)n * D_Z)[(size_t)d * 16 + (lane - 16)] = o;
    }
}

extern "C" void kernel_launch(void* const* d_in, const int* in_sizes, int n_in,
                              void* d_out, int out_size)
{
    const float* x    = (const float*)d_in[0];
    const int*   ei1  = (const int*)d_in[1];
    const int*   ei2  = (const int*)d_in[2];
    const float* W1   = (const float*)d_in[3];
    const float* b1   = (const float*)d_in[4];
    const float* Wmu  = (const float*)d_in[5];
    const float* bmu  = (const float*)d_in[6];
    const float* Wls  = (const float*)d_in[7];
    const float* bls  = (const float*)d_in[8];
    float* out = (float*)d_out;

    static cudaStream_t sB = nullptr;
    static cudaEvent_t evFork = nullptr, evJoin = nullptr;
    if (sB == nullptr) {
        cudaStreamCreateWithFlags(&sB, cudaStreamNonBlocking);
        cudaEventCreateWithFlags(&evFork, cudaEventDisableTiming);
        cudaEventCreateWithFlags(&evJoin, cudaEventDisableTiming);
    }

    float *p_dinv, *p_h;
    __half *p_g1, *p_g2;
    int *p_cnt, *p_cur, *p_rs, *p_part, *p_csr;
    cudaGetSymbolAddress((void**)&p_dinv, d_dinv);
    cudaGetSymbolAddress((void**)&p_cnt,  d_cnt);
    cudaGetSymbolAddress((void**)&p_cur,  d_cur);
    cudaGetSymbolAddress((void**)&p_rs,   d_rs);
    cudaGetSymbolAddress((void**)&p_part, d_part);
    cudaGetSymbolAddress((void**)&p_csr,  d_csr);
    cudaGetSymbolAddress((void**)&p_g1,   d_g1);
    cudaGetSymbolAddress((void**)&p_h,    d_h);
    cudaGetSymbolAddress((void**)&p_g2,   d_g2);

    const int n  = in_sizes[0] / D_IN;   // 50000
    const int E1 = in_sizes[1] / 2;      // 600000
    const int E2 = in_sizes[2] / 2;      // 200000
    const int* src1 = ei1; const int* dst1 = ei1 + E1;
    const int* src2 = ei2; const int* dst2 = ei2 + E2;

    const int T = 256;
    const int tiles = (n + 127) / 128;        // 391
    const int nblk = (n + 1023) / 1024;       // 49
    const int nq = (E1 >> 2) + (E2 >> 2);     // 200000 threads (4 edges each)

    // ---- fork: GEMM1 concurrent with CSR build ----
    cudaEventRecord(evFork, 0);
    cudaStreamWaitEvent(sB, evFork, 0);
    mma_gemm1_kernel<<<tiles, 256, 0, sB>>>(x, W1, p_g1, n);
    cudaEventRecord(evJoin, sB);

    // ---- CSR build on main stream ----
    hist2_kernel<<<(nq + T - 1) / T, T>>>(p_cnt, dst1, E1, dst2, E2);
    partial_kernel<<<nblk, 256>>>(p_cnt, p_part, n);
    scan_write_kernel<<<nblk, 256>>>(p_cnt, p_part, p_rs, p_cur, p_dinv, n, nblk);
    scatter2_kernel<<<(nq + T - 1) / T, T>>>(src1, dst1, E1, src2, dst2, E2, p_cur, p_csr);

    // ---- join, then layer-1 aggregation ----
    cudaStreamWaitEvent(0, evJoin, 0);
    agg1_kernel<<<(n * 32 + T - 1) / T, T>>>(p_rs, p_csr, p_g1, p_dinv, b1, p_h, n);

    // ---- layer 2 (fused heads) ----
    mma_gemm2_kernel<<<tiles, 256>>>(p_h, Wmu, Wls, p_dinv, p_g2, n);
    agg2_kernel<<<(n * 32 + T - 1) / T, T>>>(p_rs, p_csr, p_g2, p_dinv, bmu, bls, out, n);
}